// round 8
// baseline (speedup 1.0000x reference)
#include <cuda_runtime.h>

#define DEV_INLINE __device__ __forceinline__

namespace {
constexpr int Bb = 8, N_ = 196, D_ = 128, DFF_ = 256, C_ = 1000;
constexpr int M_ = Bb * N_;            // 1568 total rows
constexpr float NEG = -1e30f;
}

__device__ float g_h[M_ * D_];
__device__ float g_xn[M_ * D_];
__device__ float g_q[M_ * D_];
__device__ float g_k[M_ * D_];
__device__ float g_v[M_ * D_];         // v row-major (like q/k)
__device__ float g_sc[Bb * N_ * N_];   // attention scores
__device__ float g_ff[M_ * DFF_];
__device__ float g_pool[Bb * D_];

DEV_INLINE float warpMax(float v) {
#pragma unroll
    for (int m = 16; m > 0; m >>= 1)
        v = fmaxf(v, __shfl_xor_sync(0xffffffffu, v, m));
    return v;
}

// ============================================================
// GEMM (split-K2): out[m,n] = max_k(A[m,k]+W[n,k]), K=128.
// 256 threads = 2 groups of 128; group g covers K-half g.
// BM=32, BN=64, BK=32, per-thread 4x4.
// MODE 0: qkv fused; MODE 1: scores; MODE 2: ff1 (+tau)
// ============================================================
template <int MODE>
__global__ void __launch_bounds__(256) gemmA_kernel(
    const float* __restrict__ W0, const float* __restrict__ W1,
    const float* __restrict__ W2, const float* __restrict__ tau) {
    __shared__ __align__(16) float As[2][32][36];
    __shared__ __align__(16) float Ws[2][32][68];
    __shared__ __align__(16) float red[32][68];
    const int tid = threadIdx.x;
    const int wg = tid >> 7;
    const int wtid = tid & 127;
    const int m0 = blockIdx.x * 32;
    const int n0 = blockIdx.y * 64;

    const float* Ap;
    const float* Wp;
    if (MODE == 0) {
        Ap = g_xn;
        int sec = n0 >> 7;
        Wp = (sec == 0 ? W0 : (sec == 1 ? W1 : W2)) + (n0 & 127) * 128;
    } else if (MODE == 1) {
        int b = blockIdx.z;
        Ap = g_q + b * N_ * D_;
        Wp = g_k + b * N_ * D_;
    } else {
        Ap = g_xn;
        Wp = W0 + n0 * 128;
    }

    const int kq = wtid & 7, l = wtid >> 3;   // loader: 8 quads x 16 rows
    float acc[4][4];
#pragma unroll
    for (int r = 0; r < 4; r++)
#pragma unroll
        for (int c = 0; c < 4; c++) acc[r][c] = NEG;
    const int r0 = (wtid >> 4) * 4, c0 = (wtid & 15) * 4;

#pragma unroll
    for (int t = 0; t < 2; t++) {
        int k0 = wg * 64 + t * 32;
        // A tile 32x32 (rows l, l+16)
#pragma unroll
        for (int p = 0; p < 2; p++) {
            int row = l + p * 16;
            float4 av;
            if (MODE == 1 && (m0 + row) >= N_) av = make_float4(NEG, NEG, NEG, NEG);
            else av = *(const float4*)(Ap + (m0 + row) * 128 + k0 + kq * 4);
            As[wg][kq * 4 + 0][row] = av.x; As[wg][kq * 4 + 1][row] = av.y;
            As[wg][kq * 4 + 2][row] = av.z; As[wg][kq * 4 + 3][row] = av.w;
        }
        // W tile 64x32
#pragma unroll
        for (int p = 0; p < 4; p++) {
            int nl = l + p * 16;
            float4 wv;
            if (MODE == 1 && (n0 + nl) >= N_) wv = make_float4(NEG, NEG, NEG, NEG);
            else {
                int wrow = (MODE == 1) ? (n0 + nl) : nl;
                wv = *(const float4*)(Wp + wrow * 128 + k0 + kq * 4);
            }
            Ws[wg][kq * 4 + 0][nl] = wv.x; Ws[wg][kq * 4 + 1][nl] = wv.y;
            Ws[wg][kq * 4 + 2][nl] = wv.z; Ws[wg][kq * 4 + 3][nl] = wv.w;
        }
        __syncthreads();
#pragma unroll
        for (int kk = 0; kk < 32; kk++) {
            float4 a = *(const float4*)&As[wg][kk][r0];
            float4 w = *(const float4*)&Ws[wg][kk][c0];
            float ar[4] = {a.x, a.y, a.z, a.w};
            float wr[4] = {w.x, w.y, w.z, w.w};
#pragma unroll
            for (int r = 0; r < 4; r++)
#pragma unroll
                for (int c = 0; c < 4; c++)
                    acc[r][c] = fmaxf(acc[r][c], ar[r] + wr[c]);
        }
        __syncthreads();
    }

    if (wg == 1) {
#pragma unroll
        for (int r = 0; r < 4; r++)
            *(float4*)&red[r0 + r][c0] =
                make_float4(acc[r][0], acc[r][1], acc[r][2], acc[r][3]);
    }
    __syncthreads();
    if (wg == 1) return;

#pragma unroll
    for (int r = 0; r < 4; r++) {
        float4 rv = *(const float4*)&red[r0 + r][c0];
        acc[r][0] = fmaxf(acc[r][0], rv.x);
        acc[r][1] = fmaxf(acc[r][1], rv.y);
        acc[r][2] = fmaxf(acc[r][2], rv.z);
        acc[r][3] = fmaxf(acc[r][3], rv.w);
    }

    if (MODE == 0) {
#pragma unroll
        for (int r = 0; r < 4; r++) {
            int gm = m0 + r0 + r;
#pragma unroll
            for (int c = 0; c < 4; c++) {
                int gn = n0 + c0 + c;
                float v = acc[r][c];
                if (gn < 128)       g_q[gm * 128 + gn] = v;
                else if (gn < 256)  g_k[gm * 128 + (gn - 128)] = v;
                else                g_v[gm * 128 + (gn - 256)] = v;
            }
        }
    } else if (MODE == 1) {
        int b = blockIdx.z;
        float* out = g_sc + b * N_ * N_;
#pragma unroll
        for (int r = 0; r < 4; r++) {
            int i = m0 + r0 + r;
            if (i < N_) {
#pragma unroll
                for (int c = 0; c < 4; c++) {
                    int j = n0 + c0 + c;
                    if (j < N_) out[i * N_ + j] = acc[r][c];
                }
            }
        }
    } else {
        float tv = tau[0];
#pragma unroll
        for (int r = 0; r < 4; r++) {
            int gm = m0 + r0 + r;
#pragma unroll
            for (int c = 0; c < 4; c++)
                g_ff[gm * 256 + n0 + c0 + c] = fmaxf(acc[r][c], tv);
        }
    }
}

// ============================================================
// Row-fused config (split-K4): 1024 threads = 4 groups of 256.
// BM=16, BN=128, BK=16. Reduction buffers alias tile buffers.
// ============================================================
constexpr int AS_BYTES = 4 * 16 * 18 * 4;        // 4608
constexpr int WS_BYTES = 4 * 16 * 132 * 4;       // 33792
constexpr int SBUF_BYTES = AS_BYTES + WS_BYTES;  // 38400

DEV_INLINE void innerB16(const float (&As)[16][18], const float (&Ws)[16][132],
                         float (&acc)[2][4], int r0, int c0) {
#pragma unroll
    for (int kk = 0; kk < 16; kk++) {
        float a0 = As[kk][r0], a1 = As[kk][r0 + 1];
        float4 w = *(const float4*)&Ws[kk][c0];
        acc[0][0] = fmaxf(acc[0][0], a0 + w.x);
        acc[0][1] = fmaxf(acc[0][1], a0 + w.y);
        acc[0][2] = fmaxf(acc[0][2], a0 + w.z);
        acc[0][3] = fmaxf(acc[0][3], a0 + w.w);
        acc[1][0] = fmaxf(acc[1][0], a1 + w.x);
        acc[1][1] = fmaxf(acc[1][1], a1 + w.y);
        acc[1][2] = fmaxf(acc[1][2], a1 + w.z);
        acc[1][3] = fmaxf(acc[1][3], a1 + w.w);
    }
}

// embed: patchify + trop_mm(embed_W) + pos + pnorm -> g_h, g_xn. K=256 = 16 tiles.
__global__ void __launch_bounds__(1024) embed_kernel(
    const float* __restrict__ x, const float* __restrict__ eW,
    const float* __restrict__ pos) {
    __shared__ __align__(16) char sbuf[SBUF_BYTES];
    float (*As)[16][18]  = reinterpret_cast<float(*)[16][18]>(sbuf);
    float (*Ws)[16][132] = reinterpret_cast<float(*)[16][132]>(sbuf + AS_BYTES);
    float (*red)[16][132] = reinterpret_cast<float(*)[16][132]>(sbuf);  // alias (post-loop)
    const int tid = threadIdx.x;
    const int wg = tid >> 8;
    const int wtid = tid & 255;
    const int m0 = blockIdx.x * 16;
    const int r0 = (wtid >> 5) * 2, c0 = (wtid & 31) * 4;
    float acc[2][4];
#pragma unroll
    for (int r = 0; r < 2; r++)
#pragma unroll
        for (int c = 0; c < 4; c++) acc[r][c] = NEG;

#pragma unroll
    for (int t = 0; t < 4; t++) {
        int k0 = (t * 4 + wg) * 16;
        if (wtid < 64) {
            int l = wtid >> 2, kq = wtid & 3;
            int gm = m0 + l;
            int b = gm / 196, n = gm - b * 196;
            int gy = n / 14, gx = n - gy * 14;
            int k = k0 + kq * 4;
            int py = k >> 4, px = k & 15;
            float4 av = *(const float4*)(x + b * 50176 + (gy * 16 + py) * 224 + gx * 16 + px);
            As[wg][kq * 4 + 0][l] = av.x; As[wg][kq * 4 + 1][l] = av.y;
            As[wg][kq * 4 + 2][l] = av.z; As[wg][kq * 4 + 3][l] = av.w;
        }
        {
            int kq = wtid & 3, base = wtid >> 2;   // base 0..63
#pragma unroll
            for (int p = 0; p < 2; p++) {
                int nl = base + p * 64;
                float4 wv = *(const float4*)(eW + nl * 256 + k0 + kq * 4);
                Ws[wg][kq * 4 + 0][nl] = wv.x; Ws[wg][kq * 4 + 1][nl] = wv.y;
                Ws[wg][kq * 4 + 2][nl] = wv.z; Ws[wg][kq * 4 + 3][nl] = wv.w;
            }
        }
        __syncthreads();
        innerB16(As[wg], Ws[wg], acc, r0, c0);
        __syncthreads();
    }

    if (wg > 0) {
#pragma unroll
        for (int r = 0; r < 2; r++)
            *(float4*)&red[wg - 1][r0 + r][c0] =
                make_float4(acc[r][0], acc[r][1], acc[r][2], acc[r][3]);
    }
    __syncthreads();
    if (wg > 0) return;

#pragma unroll
    for (int r = 0; r < 2; r++) {
#pragma unroll
        for (int g = 0; g < 3; g++) {
            float4 rv = *(const float4*)&red[g][r0 + r][c0];
            acc[r][0] = fmaxf(acc[r][0], rv.x);
            acc[r][1] = fmaxf(acc[r][1], rv.y);
            acc[r][2] = fmaxf(acc[r][2], rv.z);
            acc[r][3] = fmaxf(acc[r][3], rv.w);
        }
        int gm = m0 + r0 + r;
        int n = gm % 196;
        float h[4];
#pragma unroll
        for (int c = 0; c < 4; c++) h[c] = acc[r][c] + pos[n * 128 + c0 + c];
        float dm = warpMax(fmaxf(fmaxf(h[0], h[1]), fmaxf(h[2], h[3])));
        int base = gm * 128 + c0;
#pragma unroll
        for (int c = 0; c < 4; c++) {
            g_h[base + c] = h[c];
            g_xn[base + c] = h[c] - dm;
        }
    }
}

// ============================================================
// attnout: o[i,d]=max_j(sc[i,j]+v[j,d])-rowmax; pnorm; residual; pnorm.
// K=196 -> 13 tiles of 16. As = score tile [i][j] (natural layout,
// direct float4 copy); Ws = v rows [j][d] (coalesced LDG.128+STS.128).
// ============================================================
constexpr int AT_AS = 4 * 16 * 20 * 4;           // 5120
constexpr int AT_WS = 4 * 16 * 132 * 4;          // 33792
constexpr int AT_SBUF = AT_AS + AT_WS;           // 38912

__global__ void __launch_bounds__(1024) attnout_kernel() {
    __shared__ __align__(16) char sbuf[AT_SBUF];
    float (*As)[16][20]  = reinterpret_cast<float(*)[16][20]>(sbuf);
    float (*Ws)[16][132] = reinterpret_cast<float(*)[16][132]>(sbuf + AT_AS);
    float (*red)[16][132] = reinterpret_cast<float(*)[16][132]>(sbuf);  // alias
    __shared__ float redrm[3][16];
    const int tid = threadIdx.x;
    const int wg = tid >> 8;
    const int wtid = tid & 255;
    const int b = blockIdx.y;
    const int m0 = blockIdx.x * 16;
    const float* Ap = g_sc + b * N_ * N_;
    const float* Vp = g_v + b * N_ * D_;
    const int r0 = (wtid >> 5) * 2, c0 = (wtid & 31) * 4;
    float acc[2][4];
    float rm[2] = {NEG, NEG};
#pragma unroll
    for (int r = 0; r < 2; r++)
#pragma unroll
        for (int c = 0; c < 4; c++) acc[r][c] = NEG;

#pragma unroll
    for (int t = 0; t < 4; t++) {
        int j0 = (t * 4 + wg) * 16;
        bool tvalid = j0 < N_;
        if (tvalid) {
            if (wtid < 64) {
                // score tile: As[l][jq*4..+3] direct copy (no transpose)
                int l = wtid >> 2, jq = wtid & 3;
                int gm = m0 + l;
                int j = j0 + jq * 4;
                float4 av = (gm < N_ && j < N_)
                                ? *(const float4*)(Ap + gm * N_ + j)
                                : make_float4(NEG, NEG, NEG, NEG);
                *(float4*)&As[wg][l][jq * 4] = av;
            }
            {
                // v tile: Ws[jj][d] from row-major v (coalesced)
                int jj = wtid >> 4, dq = wtid & 15;
                int j = j0 + jj;
                const float* vrow = Vp + j * 128;
                bool jv = j < N_;
#pragma unroll
                for (int p = 0; p < 2; p++) {
                    int d0 = dq * 4 + p * 64;
                    float4 vv = jv ? *(const float4*)(vrow + d0)
                                   : make_float4(NEG, NEG, NEG, NEG);
                    *(float4*)&Ws[wg][jj][d0] = vv;
                }
            }
        }
        __syncthreads();
        if (tvalid) {
#pragma unroll
            for (int kk = 0; kk < 16; kk++) {
                float a0 = As[wg][r0][kk], a1 = As[wg][r0 + 1][kk];
                rm[0] = fmaxf(rm[0], a0); rm[1] = fmaxf(rm[1], a1);
                float4 w = *(const float4*)&Ws[wg][kk][c0];
                acc[0][0] = fmaxf(acc[0][0], a0 + w.x);
                acc[0][1] = fmaxf(acc[0][1], a0 + w.y);
                acc[0][2] = fmaxf(acc[0][2], a0 + w.z);
                acc[0][3] = fmaxf(acc[0][3], a0 + w.w);
                acc[1][0] = fmaxf(acc[1][0], a1 + w.x);
                acc[1][1] = fmaxf(acc[1][1], a1 + w.y);
                acc[1][2] = fmaxf(acc[1][2], a1 + w.z);
                acc[1][3] = fmaxf(acc[1][3], a1 + w.w);
            }
        }
        __syncthreads();
    }

    if (wg > 0) {
#pragma unroll
        for (int r = 0; r < 2; r++) {
            *(float4*)&red[wg - 1][r0 + r][c0] =
                make_float4(acc[r][0], acc[r][1], acc[r][2], acc[r][3]);
            if ((wtid & 31) == 0) redrm[wg - 1][r0 + r] = rm[r];
        }
    }
    __syncthreads();
    if (wg > 0) return;

#pragma unroll
    for (int r = 0; r < 2; r++) {
        int i = m0 + r0 + r;
        if (i < N_) {
            float frm = rm[r];
#pragma unroll
            for (int g = 0; g < 3; g++) {
                frm = fmaxf(frm, redrm[g][r0 + r]);
                float4 rv = *(const float4*)&red[g][r0 + r][c0];
                acc[r][0] = fmaxf(acc[r][0], rv.x);
                acc[r][1] = fmaxf(acc[r][1], rv.y);
                acc[r][2] = fmaxf(acc[r][2], rv.z);
                acc[r][3] = fmaxf(acc[r][3], rv.w);
            }
            float o[4];
#pragma unroll
            for (int c = 0; c < 4; c++) o[c] = acc[r][c] - frm;
            float dm = warpMax(fmaxf(fmaxf(o[0], o[1]), fmaxf(o[2], o[3])));
            int base = (b * 196 + i) * 128 + c0;
            float nx[4];
#pragma unroll
            for (int c = 0; c < 4; c++)
                nx[c] = fmaxf(g_h[base + c], o[c] - dm);
            float dm2 = warpMax(fmaxf(fmaxf(nx[0], nx[1]), fmaxf(nx[2], nx[3])));
#pragma unroll
            for (int c = 0; c < 4; c++) {
                g_h[base + c] = nx[c];
                g_xn[base + c] = nx[c] - dm2;
            }
        }
    }
}

// ff2: trop_mm(g_ff, f2W), K=256 = 16 tiles; pnorm; residual; pnorm.
__global__ void __launch_bounds__(1024) ff2_kernel(const float* __restrict__ W) {
    __shared__ __align__(16) char sbuf[SBUF_BYTES];
    float (*As)[16][18]  = reinterpret_cast<float(*)[16][18]>(sbuf);
    float (*Ws)[16][132] = reinterpret_cast<float(*)[16][132]>(sbuf + AS_BYTES);
    float (*red)[16][132] = reinterpret_cast<float(*)[16][132]>(sbuf);
    const int tid = threadIdx.x;
    const int wg = tid >> 8;
    const int wtid = tid & 255;
    const int m0 = blockIdx.x * 16;
    const int r0 = (wtid >> 5) * 2, c0 = (wtid & 31) * 4;
    float acc[2][4];
#pragma unroll
    for (int r = 0; r < 2; r++)
#pragma unroll
        for (int c = 0; c < 4; c++) acc[r][c] = NEG;

#pragma unroll
    for (int t = 0; t < 4; t++) {
        int k0 = (t * 4 + wg) * 16;
        if (wtid < 64) {
            int l = wtid >> 2, kq = wtid & 3;
            float4 av = *(const float4*)(g_ff + (m0 + l) * 256 + k0 + kq * 4);
            As[wg][kq * 4 + 0][l] = av.x; As[wg][kq * 4 + 1][l] = av.y;
            As[wg][kq * 4 + 2][l] = av.z; As[wg][kq * 4 + 3][l] = av.w;
        }
        {
            int kq = wtid & 3, base = wtid >> 2;
#pragma unroll
            for (int p = 0; p < 2; p++) {
                int nl = base + p * 64;
                float4 wv = *(const float4*)(W + nl * 256 + k0 + kq * 4);
                Ws[wg][kq * 4 + 0][nl] = wv.x; Ws[wg][kq * 4 + 1][nl] = wv.y;
                Ws[wg][kq * 4 + 2][nl] = wv.z; Ws[wg][kq * 4 + 3][nl] = wv.w;
            }
        }
        __syncthreads();
        innerB16(As[wg], Ws[wg], acc, r0, c0);
        __syncthreads();
    }

    if (wg > 0) {
#pragma unroll
        for (int r = 0; r < 2; r++)
            *(float4*)&red[wg - 1][r0 + r][c0] =
                make_float4(acc[r][0], acc[r][1], acc[r][2], acc[r][3]);
    }
    __syncthreads();
    if (wg > 0) return;

#pragma unroll
    for (int r = 0; r < 2; r++) {
#pragma unroll
        for (int g = 0; g < 3; g++) {
            float4 rv = *(const float4*)&red[g][r0 + r][c0];
            acc[r][0] = fmaxf(acc[r][0], rv.x);
            acc[r][1] = fmaxf(acc[r][1], rv.y);
            acc[r][2] = fmaxf(acc[r][2], rv.z);
            acc[r][3] = fmaxf(acc[r][3], rv.w);
        }
        int gm = m0 + r0 + r;
        float dm = warpMax(fmaxf(fmaxf(acc[r][0], acc[r][1]), fmaxf(acc[r][2], acc[r][3])));
        int base = gm * 128 + c0;
        float nx[4];
#pragma unroll
        for (int c = 0; c < 4; c++)
            nx[c] = fmaxf(g_h[base + c], acc[r][c] - dm);
        float dm2 = warpMax(fmaxf(fmaxf(nx[0], nx[1]), fmaxf(nx[2], nx[3])));
#pragma unroll
        for (int c = 0; c < 4; c++) {
            g_h[base + c] = nx[c];
            g_xn[base + c] = nx[c] - dm2;
        }
    }
}

__global__ void __launch_bounds__(512) pool_kernel() {
    __shared__ float sm[4][128];
    int b = blockIdx.x;
    int d = threadIdx.x & 127;
    int q = threadIdx.x >> 7;
    float m = NEG;
    for (int n = q; n < N_; n += 4)
        m = fmaxf(m, g_h[(b * N_ + n) * D_ + d]);
    sm[q][d] = m;
    __syncthreads();
    if (q == 0) {
        m = fmaxf(fmaxf(sm[0][d], sm[1][d]), fmaxf(sm[2][d], sm[3][d]));
        g_pool[b * D_ + d] = m;
    }
}

__global__ void __launch_bounds__(256) head_kernel(
    const float* __restrict__ hW, const float* __restrict__ ls,
    float* __restrict__ out) {
    __shared__ float sp[128];
    const int b = blockIdx.y;
    const int tid = threadIdx.x;
    if (tid < 128) sp[tid] = g_pool[b * 128 + tid];
    __syncthreads();
    int c = blockIdx.x * 256 + tid;
    if (c < C_) {
        float acc = NEG;
#pragma unroll 8
        for (int d = 0; d < 128; d += 4) {
            float4 w = *(const float4*)(hW + c * 128 + d);
            acc = fmaxf(acc, sp[d + 0] + w.x);
            acc = fmaxf(acc, sp[d + 1] + w.y);
            acc = fmaxf(acc, sp[d + 2] + w.z);
            acc = fmaxf(acc, sp[d + 3] + w.w);
        }
        out[b * C_ + c] = acc * ls[0];
    }
}

extern "C" void kernel_launch(void* const* d_in, const int* in_sizes, int n_in,
                              void* d_out, int out_size) {
    const float* x   = (const float*)d_in[0];
    const float* eW  = (const float*)d_in[1];
    const float* pos = (const float*)d_in[2];
    const float* qW[2]  = {(const float*)d_in[3],  (const float*)d_in[9]};
    const float* kW[2]  = {(const float*)d_in[4],  (const float*)d_in[10]};
    const float* vW[2]  = {(const float*)d_in[5],  (const float*)d_in[11]};
    const float* f1[2]  = {(const float*)d_in[6],  (const float*)d_in[12]};
    const float* f2[2]  = {(const float*)d_in[7],  (const float*)d_in[13]};
    const float* tau[2] = {(const float*)d_in[8],  (const float*)d_in[14]};
    const float* hW = (const float*)d_in[15];
    const float* ls = (const float*)d_in[16];
    float* out = (float*)d_out;

    embed_kernel<<<98, 1024>>>(x, eW, pos);
    for (int l = 0; l < 2; l++) {
        gemmA_kernel<0><<<dim3(49, 6), 256>>>(qW[l], kW[l], vW[l], nullptr);
        gemmA_kernel<1><<<dim3(7, 4, 8), 256>>>(nullptr, nullptr, nullptr, nullptr);
        attnout_kernel<<<dim3(13, 8), 1024>>>();
        gemmA_kernel<2><<<dim3(49, 4), 256>>>(f1[l], nullptr, nullptr, tau[l]);
        ff2_kernel<<<98, 1024>>>(f2[l]);
    }
    pool_kernel<<<8, 512>>>();
    head_kernel<<<dim3(4, 8), 256>>>(hW, ls, out);
}

// round 9
// speedup vs baseline: 1.5215x; 1.5215x over previous
#include <cuda_runtime.h>

#define DEV_INLINE __device__ __forceinline__

namespace {
constexpr int Bb = 8, N_ = 196, D_ = 128, DFF_ = 256, C_ = 1000;
constexpr int M_ = Bb * N_;            // 1568 total rows
constexpr float NEG = -1e30f;
}

__device__ float g_h[M_ * D_];
__device__ float g_xn[M_ * D_];
__device__ float g_q[M_ * D_];
__device__ float g_k[M_ * D_];
__device__ float g_v[M_ * D_];         // v row-major (like q/k)
__device__ float g_sc[Bb * N_ * N_];   // attention scores
__device__ float g_ff[M_ * DFF_];
__device__ float g_pool[Bb * D_];

DEV_INLINE float warpMax(float v) {
#pragma unroll
    for (int m = 16; m > 0; m >>= 1)
        v = fmaxf(v, __shfl_xor_sync(0xffffffffu, v, m));
    return v;
}

// ============================================================
// GEMM (split-K2): out[m,n] = max_k(A[m,k]+W[n,k]), K=128.
// 256 threads = 2 groups of 128; group g covers K-half g.
// BM=32, BN=64, BK=32, per-thread 4x4.
// MODE 0: qkv fused; MODE 1: scores; MODE 2: ff1 (+tau)
// ============================================================
template <int MODE>
__global__ void __launch_bounds__(256) gemmA_kernel(
    const float* __restrict__ W0, const float* __restrict__ W1,
    const float* __restrict__ W2, const float* __restrict__ tau) {
    __shared__ __align__(16) float As[2][32][36];
    __shared__ __align__(16) float Ws[2][32][68];
    __shared__ __align__(16) float red[32][68];
    const int tid = threadIdx.x;
    const int wg = tid >> 7;
    const int wtid = tid & 127;
    const int m0 = blockIdx.x * 32;
    const int n0 = blockIdx.y * 64;

    const float* Ap;
    const float* Wp;
    if (MODE == 0) {
        Ap = g_xn;
        int sec = n0 >> 7;
        Wp = (sec == 0 ? W0 : (sec == 1 ? W1 : W2)) + (n0 & 127) * 128;
    } else if (MODE == 1) {
        int b = blockIdx.z;
        Ap = g_q + b * N_ * D_;
        Wp = g_k + b * N_ * D_;
    } else {
        Ap = g_xn;
        Wp = W0 + n0 * 128;
    }

    const int kq = wtid & 7, l = wtid >> 3;   // loader: 8 quads x 16 rows
    float acc[4][4];
#pragma unroll
    for (int r = 0; r < 4; r++)
#pragma unroll
        for (int c = 0; c < 4; c++) acc[r][c] = NEG;
    const int r0 = (wtid >> 4) * 4, c0 = (wtid & 15) * 4;

#pragma unroll
    for (int t = 0; t < 2; t++) {
        int k0 = wg * 64 + t * 32;
        // A tile 32x32 (rows l, l+16)
#pragma unroll
        for (int p = 0; p < 2; p++) {
            int row = l + p * 16;
            float4 av;
            if (MODE == 1 && (m0 + row) >= N_) av = make_float4(NEG, NEG, NEG, NEG);
            else av = *(const float4*)(Ap + (m0 + row) * 128 + k0 + kq * 4);
            As[wg][kq * 4 + 0][row] = av.x; As[wg][kq * 4 + 1][row] = av.y;
            As[wg][kq * 4 + 2][row] = av.z; As[wg][kq * 4 + 3][row] = av.w;
        }
        // W tile 64x32
#pragma unroll
        for (int p = 0; p < 4; p++) {
            int nl = l + p * 16;
            float4 wv;
            if (MODE == 1 && (n0 + nl) >= N_) wv = make_float4(NEG, NEG, NEG, NEG);
            else {
                int wrow = (MODE == 1) ? (n0 + nl) : nl;
                wv = *(const float4*)(Wp + wrow * 128 + k0 + kq * 4);
            }
            Ws[wg][kq * 4 + 0][nl] = wv.x; Ws[wg][kq * 4 + 1][nl] = wv.y;
            Ws[wg][kq * 4 + 2][nl] = wv.z; Ws[wg][kq * 4 + 3][nl] = wv.w;
        }
        __syncthreads();
#pragma unroll
        for (int kk = 0; kk < 32; kk++) {
            float4 a = *(const float4*)&As[wg][kk][r0];
            float4 w = *(const float4*)&Ws[wg][kk][c0];
            float ar[4] = {a.x, a.y, a.z, a.w};
            float wr[4] = {w.x, w.y, w.z, w.w};
#pragma unroll
            for (int r = 0; r < 4; r++)
#pragma unroll
                for (int c = 0; c < 4; c++)
                    acc[r][c] = fmaxf(acc[r][c], ar[r] + wr[c]);
        }
        __syncthreads();
    }

    if (wg == 1) {
#pragma unroll
        for (int r = 0; r < 4; r++)
            *(float4*)&red[r0 + r][c0] =
                make_float4(acc[r][0], acc[r][1], acc[r][2], acc[r][3]);
    }
    __syncthreads();
    if (wg == 1) return;

#pragma unroll
    for (int r = 0; r < 4; r++) {
        float4 rv = *(const float4*)&red[r0 + r][c0];
        acc[r][0] = fmaxf(acc[r][0], rv.x);
        acc[r][1] = fmaxf(acc[r][1], rv.y);
        acc[r][2] = fmaxf(acc[r][2], rv.z);
        acc[r][3] = fmaxf(acc[r][3], rv.w);
    }

    if (MODE == 0) {
#pragma unroll
        for (int r = 0; r < 4; r++) {
            int gm = m0 + r0 + r;
#pragma unroll
            for (int c = 0; c < 4; c++) {
                int gn = n0 + c0 + c;
                float v = acc[r][c];
                if (gn < 128)       g_q[gm * 128 + gn] = v;
                else if (gn < 256)  g_k[gm * 128 + (gn - 128)] = v;
                else                g_v[gm * 128 + (gn - 256)] = v;
            }
        }
    } else if (MODE == 1) {
        int b = blockIdx.z;
        float* out = g_sc + b * N_ * N_;
#pragma unroll
        for (int r = 0; r < 4; r++) {
            int i = m0 + r0 + r;
            if (i < N_) {
#pragma unroll
                for (int c = 0; c < 4; c++) {
                    int j = n0 + c0 + c;
                    if (j < N_) out[i * N_ + j] = acc[r][c];
                }
            }
        }
    } else {
        float tv = tau[0];
#pragma unroll
        for (int r = 0; r < 4; r++) {
            int gm = m0 + r0 + r;
#pragma unroll
            for (int c = 0; c < 4; c++)
                g_ff[gm * 256 + n0 + c0 + c] = fmaxf(acc[r][c], tv);
        }
    }
}

// ============================================================
// Row-fused config (split-K4): 1024 threads = 4 groups of 256.
// BM=16, BN=128, BK=16. Reduction buffers alias tile buffers.
// (embed / ff2 — R7 proven config)
// ============================================================
constexpr int AS_BYTES = 4 * 16 * 18 * 4;        // 4608
constexpr int WS_BYTES = 4 * 16 * 132 * 4;       // 33792
constexpr int SBUF_BYTES = AS_BYTES + WS_BYTES;  // 38400

DEV_INLINE void innerB16(const float (&As)[16][18], const float (&Ws)[16][132],
                         float (&acc)[2][4], int r0, int c0) {
#pragma unroll
    for (int kk = 0; kk < 16; kk++) {
        float a0 = As[kk][r0], a1 = As[kk][r0 + 1];
        float4 w = *(const float4*)&Ws[kk][c0];
        acc[0][0] = fmaxf(acc[0][0], a0 + w.x);
        acc[0][1] = fmaxf(acc[0][1], a0 + w.y);
        acc[0][2] = fmaxf(acc[0][2], a0 + w.z);
        acc[0][3] = fmaxf(acc[0][3], a0 + w.w);
        acc[1][0] = fmaxf(acc[1][0], a1 + w.x);
        acc[1][1] = fmaxf(acc[1][1], a1 + w.y);
        acc[1][2] = fmaxf(acc[1][2], a1 + w.z);
        acc[1][3] = fmaxf(acc[1][3], a1 + w.w);
    }
}

// embed: patchify + trop_mm(embed_W) + pos + pnorm -> g_h, g_xn. K=256 = 16 tiles.
__global__ void __launch_bounds__(1024) embed_kernel(
    const float* __restrict__ x, const float* __restrict__ eW,
    const float* __restrict__ pos) {
    __shared__ __align__(16) char sbuf[SBUF_BYTES];
    float (*As)[16][18]  = reinterpret_cast<float(*)[16][18]>(sbuf);
    float (*Ws)[16][132] = reinterpret_cast<float(*)[16][132]>(sbuf + AS_BYTES);
    float (*red)[16][132] = reinterpret_cast<float(*)[16][132]>(sbuf);  // alias (post-loop)
    const int tid = threadIdx.x;
    const int wg = tid >> 8;
    const int wtid = tid & 255;
    const int m0 = blockIdx.x * 16;
    const int r0 = (wtid >> 5) * 2, c0 = (wtid & 31) * 4;
    float acc[2][4];
#pragma unroll
    for (int r = 0; r < 2; r++)
#pragma unroll
        for (int c = 0; c < 4; c++) acc[r][c] = NEG;

#pragma unroll
    for (int t = 0; t < 4; t++) {
        int k0 = (t * 4 + wg) * 16;
        if (wtid < 64) {
            int l = wtid >> 2, kq = wtid & 3;
            int gm = m0 + l;
            int b = gm / 196, n = gm - b * 196;
            int gy = n / 14, gx = n - gy * 14;
            int k = k0 + kq * 4;
            int py = k >> 4, px = k & 15;
            float4 av = *(const float4*)(x + b * 50176 + (gy * 16 + py) * 224 + gx * 16 + px);
            As[wg][kq * 4 + 0][l] = av.x; As[wg][kq * 4 + 1][l] = av.y;
            As[wg][kq * 4 + 2][l] = av.z; As[wg][kq * 4 + 3][l] = av.w;
        }
        {
            int kq = wtid & 3, base = wtid >> 2;   // base 0..63
#pragma unroll
            for (int p = 0; p < 2; p++) {
                int nl = base + p * 64;
                float4 wv = *(const float4*)(eW + nl * 256 + k0 + kq * 4);
                Ws[wg][kq * 4 + 0][nl] = wv.x; Ws[wg][kq * 4 + 1][nl] = wv.y;
                Ws[wg][kq * 4 + 2][nl] = wv.z; Ws[wg][kq * 4 + 3][nl] = wv.w;
            }
        }
        __syncthreads();
        innerB16(As[wg], Ws[wg], acc, r0, c0);
        __syncthreads();
    }

    if (wg > 0) {
#pragma unroll
        for (int r = 0; r < 2; r++)
            *(float4*)&red[wg - 1][r0 + r][c0] =
                make_float4(acc[r][0], acc[r][1], acc[r][2], acc[r][3]);
    }
    __syncthreads();
    if (wg > 0) return;

#pragma unroll
    for (int r = 0; r < 2; r++) {
#pragma unroll
        for (int g = 0; g < 3; g++) {
            float4 rv = *(const float4*)&red[g][r0 + r][c0];
            acc[r][0] = fmaxf(acc[r][0], rv.x);
            acc[r][1] = fmaxf(acc[r][1], rv.y);
            acc[r][2] = fmaxf(acc[r][2], rv.z);
            acc[r][3] = fmaxf(acc[r][3], rv.w);
        }
        int gm = m0 + r0 + r;
        int n = gm % 196;
        float h[4];
#pragma unroll
        for (int c = 0; c < 4; c++) h[c] = acc[r][c] + pos[n * 128 + c0 + c];
        float dm = warpMax(fmaxf(fmaxf(h[0], h[1]), fmaxf(h[2], h[3])));
        int base = gm * 128 + c0;
#pragma unroll
        for (int c = 0; c < 4; c++) {
            g_h[base + c] = h[c];
            g_xn[base + c] = h[c] - dm;
        }
    }
}

// ============================================================
// attnout v2: FULL-K-RESIDENT. One batch, 16 q-rows per block.
// Stage V[196][128] (natural row-major, coalesced) + scores
// transposed Ss[196][16] into 119KB dynamic smem ONCE; then
// 8 groups x 128 threads each contract their ~25-j range with a
// 4x4 register tile — no barriers in the mainloop.
// rowmax recomputed from Ss in the epilogue (off the hot loop).
// ============================================================
constexpr int VS_F = 132;                       // padded V row (floats)
constexpr int SS_F = 20;                        // padded score-T row (80B, 16B-aligned)
constexpr int ATT_DYN = (N_ * VS_F + N_ * SS_F) * 4;   // 119,168 B

__global__ void __launch_bounds__(1024) attnout_kernel() {
    extern __shared__ __align__(16) float smem[];
    float* Vs = smem;                 // [196][VS_F]
    float* Ss = smem + N_ * VS_F;     // [196][SS_F]
    float* red = smem;                // alias over Vs post-mainloop: [7][16][VS_F]

    const int tid = threadIdx.x;
    const int b = blockIdx.y;
    const int m0 = blockIdx.x * 16;
    const float* Ap = g_sc + b * N_ * N_;
    const float* Vp = g_v + b * N_ * D_;

    // ---- stage V (coalesced float4, no transpose) ----
    for (int idx = tid; idx < N_ * 32; idx += 1024) {
        int j = idx >> 5, q = idx & 31;
        *(float4*)(Vs + j * VS_F + q * 4) = *(const float4*)(Vp + j * 128 + q * 4);
    }
    // ---- stage scores transposed: Ss[j][i] ----
    if (tid < 16 * 49) {
        int i = tid / 49, jq = tid - i * 49;
        int gi = m0 + i;
        float4 s = (gi < N_) ? *(const float4*)(Ap + gi * N_ + jq * 4)
                             : make_float4(NEG, NEG, NEG, NEG);
        Ss[(jq * 4 + 0) * SS_F + i] = s.x;
        Ss[(jq * 4 + 1) * SS_F + i] = s.y;
        Ss[(jq * 4 + 2) * SS_F + i] = s.z;
        Ss[(jq * 4 + 3) * SS_F + i] = s.w;
    }
    __syncthreads();                                   // barrier 1

    const int wg = tid >> 7;          // 0..7
    const int wt = tid & 127;
    const int r0 = (wt >> 5) * 4;     // warp-in-group -> 4 rows
    const int c0 = (wt & 31) * 4;     // lane -> 4 d-cols
    const int jlo = wg * 24 + (wg < 4 ? wg : 4);
    const int jcnt = 24 + (wg < 4 ? 1 : 0);

    float acc[4][4];
#pragma unroll
    for (int r = 0; r < 4; r++)
#pragma unroll
        for (int c = 0; c < 4; c++) acc[r][c] = NEG;

    const float* ssp = Ss + jlo * SS_F + r0;
    const float* vsp = Vs + jlo * VS_F + c0;
#pragma unroll 5
    for (int t = 0; t < jcnt; t++) {
        float4 a = *(const float4*)ssp;  ssp += SS_F;
        float4 w = *(const float4*)vsp;  vsp += VS_F;
        float ar[4] = {a.x, a.y, a.z, a.w};
        float wr[4] = {w.x, w.y, w.z, w.w};
#pragma unroll
        for (int r = 0; r < 4; r++)
#pragma unroll
            for (int c = 0; c < 4; c++)
                acc[r][c] = fmaxf(acc[r][c], ar[r] + wr[c]);
    }
    __syncthreads();                                   // barrier 2 (Vs dead)

    if (wg > 0) {
#pragma unroll
        for (int r = 0; r < 4; r++)
            *(float4*)(red + ((wg - 1) * 16 + r0 + r) * VS_F + c0) =
                make_float4(acc[r][0], acc[r][1], acc[r][2], acc[r][3]);
    }
    __syncthreads();                                   // barrier 3
    if (wg > 0) return;

    // ---- group 0: reduce partials + rowmax + pnorm + residual + pnorm ----
    const int lane = wt & 31;
#pragma unroll
    for (int r = 0; r < 4; r++) {
        int i = m0 + r0 + r;
        if (i < N_) {                                  // warp-uniform
#pragma unroll
            for (int g = 0; g < 7; g++) {
                float4 rv = *(const float4*)(red + (g * 16 + r0 + r) * VS_F + c0);
                acc[r][0] = fmaxf(acc[r][0], rv.x);
                acc[r][1] = fmaxf(acc[r][1], rv.y);
                acc[r][2] = fmaxf(acc[r][2], rv.z);
                acc[r][3] = fmaxf(acc[r][3], rv.w);
            }
            float rm = NEG;
            for (int j = lane; j < N_; j += 32)
                rm = fmaxf(rm, Ss[j * SS_F + r0 + r]);
            rm = warpMax(rm);
            float o[4];
#pragma unroll
            for (int c = 0; c < 4; c++) o[c] = acc[r][c] - rm;
            float dm = warpMax(fmaxf(fmaxf(o[0], o[1]), fmaxf(o[2], o[3])));
            int base = (b * 196 + i) * 128 + c0;
            float nx[4];
#pragma unroll
            for (int c = 0; c < 4; c++)
                nx[c] = fmaxf(g_h[base + c], o[c] - dm);
            float dm2 = warpMax(fmaxf(fmaxf(nx[0], nx[1]), fmaxf(nx[2], nx[3])));
#pragma unroll
            for (int c = 0; c < 4; c++) {
                g_h[base + c] = nx[c];
                g_xn[base + c] = nx[c] - dm2;
            }
        }
    }
}

// ff2: trop_mm(g_ff, f2W), K=256 = 16 tiles; pnorm; residual; pnorm.
__global__ void __launch_bounds__(1024) ff2_kernel(const float* __restrict__ W) {
    __shared__ __align__(16) char sbuf[SBUF_BYTES];
    float (*As)[16][18]  = reinterpret_cast<float(*)[16][18]>(sbuf);
    float (*Ws)[16][132] = reinterpret_cast<float(*)[16][132]>(sbuf + AS_BYTES);
    float (*red)[16][132] = reinterpret_cast<float(*)[16][132]>(sbuf);
    const int tid = threadIdx.x;
    const int wg = tid >> 8;
    const int wtid = tid & 255;
    const int m0 = blockIdx.x * 16;
    const int r0 = (wtid >> 5) * 2, c0 = (wtid & 31) * 4;
    float acc[2][4];
#pragma unroll
    for (int r = 0; r < 2; r++)
#pragma unroll
        for (int c = 0; c < 4; c++) acc[r][c] = NEG;

#pragma unroll
    for (int t = 0; t < 4; t++) {
        int k0 = (t * 4 + wg) * 16;
        if (wtid < 64) {
            int l = wtid >> 2, kq = wtid & 3;
            float4 av = *(const float4*)(g_ff + (m0 + l) * 256 + k0 + kq * 4);
            As[wg][kq * 4 + 0][l] = av.x; As[wg][kq * 4 + 1][l] = av.y;
            As[wg][kq * 4 + 2][l] = av.z; As[wg][kq * 4 + 3][l] = av.w;
        }
        {
            int kq = wtid & 3, base = wtid >> 2;
#pragma unroll
            for (int p = 0; p < 2; p++) {
                int nl = base + p * 64;
                float4 wv = *(const float4*)(W + nl * 256 + k0 + kq * 4);
                Ws[wg][kq * 4 + 0][nl] = wv.x; Ws[wg][kq * 4 + 1][nl] = wv.y;
                Ws[wg][kq * 4 + 2][nl] = wv.z; Ws[wg][kq * 4 + 3][nl] = wv.w;
            }
        }
        __syncthreads();
        innerB16(As[wg], Ws[wg], acc, r0, c0);
        __syncthreads();
    }

    if (wg > 0) {
#pragma unroll
        for (int r = 0; r < 2; r++)
            *(float4*)&red[wg - 1][r0 + r][c0] =
                make_float4(acc[r][0], acc[r][1], acc[r][2], acc[r][3]);
    }
    __syncthreads();
    if (wg > 0) return;

#pragma unroll
    for (int r = 0; r < 2; r++) {
#pragma unroll
        for (int g = 0; g < 3; g++) {
            float4 rv = *(const float4*)&red[g][r0 + r][c0];
            acc[r][0] = fmaxf(acc[r][0], rv.x);
            acc[r][1] = fmaxf(acc[r][1], rv.y);
            acc[r][2] = fmaxf(acc[r][2], rv.z);
            acc[r][3] = fmaxf(acc[r][3], rv.w);
        }
        int gm = m0 + r0 + r;
        float dm = warpMax(fmaxf(fmaxf(acc[r][0], acc[r][1]), fmaxf(acc[r][2], acc[r][3])));
        int base = gm * 128 + c0;
        float nx[4];
#pragma unroll
        for (int c = 0; c < 4; c++)
            nx[c] = fmaxf(g_h[base + c], acc[r][c] - dm);
        float dm2 = warpMax(fmaxf(fmaxf(nx[0], nx[1]), fmaxf(nx[2], nx[3])));
#pragma unroll
        for (int c = 0; c < 4; c++) {
            g_h[base + c] = nx[c];
            g_xn[base + c] = nx[c] - dm2;
        }
    }
}

__global__ void __launch_bounds__(512) pool_kernel() {
    __shared__ float sm[4][128];
    int b = blockIdx.x;
    int d = threadIdx.x & 127;
    int q = threadIdx.x >> 7;
    float m = NEG;
    for (int n = q; n < N_; n += 4)
        m = fmaxf(m, g_h[(b * N_ + n) * D_ + d]);
    sm[q][d] = m;
    __syncthreads();
    if (q == 0) {
        m = fmaxf(fmaxf(sm[0][d], sm[1][d]), fmaxf(sm[2][d], sm[3][d]));
        g_pool[b * D_ + d] = m;
    }
}

__global__ void __launch_bounds__(256) head_kernel(
    const float* __restrict__ hW, const float* __restrict__ ls,
    float* __restrict__ out) {
    __shared__ float sp[128];
    const int b = blockIdx.y;
    const int tid = threadIdx.x;
    if (tid < 128) sp[tid] = g_pool[b * 128 + tid];
    __syncthreads();
    int c = blockIdx.x * 256 + tid;
    if (c < C_) {
        float acc = NEG;
#pragma unroll 8
        for (int d = 0; d < 128; d += 4) {
            float4 w = *(const float4*)(hW + c * 128 + d);
            acc = fmaxf(acc, sp[d + 0] + w.x);
            acc = fmaxf(acc, sp[d + 1] + w.y);
            acc = fmaxf(acc, sp[d + 2] + w.z);
            acc = fmaxf(acc, sp[d + 3] + w.w);
        }
        out[b * C_ + c] = acc * ls[0];
    }
}

extern "C" void kernel_launch(void* const* d_in, const int* in_sizes, int n_in,
                              void* d_out, int out_size) {
    const float* x   = (const float*)d_in[0];
    const float* eW  = (const float*)d_in[1];
    const float* pos = (const float*)d_in[2];
    const float* qW[2]  = {(const float*)d_in[3],  (const float*)d_in[9]};
    const float* kW[2]  = {(const float*)d_in[4],  (const float*)d_in[10]};
    const float* vW[2]  = {(const float*)d_in[5],  (const float*)d_in[11]};
    const float* f1[2]  = {(const float*)d_in[6],  (const float*)d_in[12]};
    const float* f2[2]  = {(const float*)d_in[7],  (const float*)d_in[13]};
    const float* tau[2] = {(const float*)d_in[8],  (const float*)d_in[14]};
    const float* hW = (const float*)d_in[15];
    const float* ls = (const float*)d_in[16];
    float* out = (float*)d_out;

    cudaFuncSetAttribute(attnout_kernel,
                         cudaFuncAttributeMaxDynamicSharedMemorySize, ATT_DYN);

    embed_kernel<<<98, 1024>>>(x, eW, pos);
    for (int l = 0; l < 2; l++) {
        gemmA_kernel<0><<<dim3(49, 6), 256>>>(qW[l], kW[l], vW[l], nullptr);
        gemmA_kernel<1><<<dim3(7, 4, 8), 256>>>(nullptr, nullptr, nullptr, nullptr);
        attnout_kernel<<<dim3(13, 8), 1024, ATT_DYN>>>();
        gemmA_kernel<2><<<dim3(49, 4), 256>>>(f1[l], nullptr, nullptr, tau[l]);
        ff2_kernel<<<98, 1024>>>(f2[l]);
    }
    pool_kernel<<<8, 512>>>();
    head_kernel<<<dim3(4, 8), 256>>>(hW, ls, out);
}

// round 14
// speedup vs baseline: 1.6208x; 1.0652x over previous
#include <cuda_runtime.h>

#define DEV_INLINE __device__ __forceinline__

namespace {
constexpr int Bb = 8, N_ = 196, D_ = 128, DFF_ = 256, C_ = 1000;
constexpr int M_ = Bb * N_;            // 1568 total rows
constexpr float NEG = -1e30f;
}

__device__ float g_h[M_ * D_];
__device__ float g_xn[M_ * D_];
__device__ float g_q[M_ * D_];
__device__ float g_k[M_ * D_];
__device__ float g_v[M_ * D_];         // v row-major (like q/k)
__device__ float g_sc[Bb * N_ * N_];   // attention scores
__device__ float g_ff[M_ * DFF_];
__device__ float g_pool[Bb * D_];

DEV_INLINE float warpMax(float v) {
#pragma unroll
    for (int m = 16; m > 0; m >>= 1)
        v = fmaxf(v, __shfl_xor_sync(0xffffffffu, v, m));
    return v;
}

// ============================================================
// GEMM (split-K2, front-loaded): out[m,n] = max_k(A[m,k]+W[n,k]),
// K=128. 256 threads = 2 groups of 128; BM=32, BN=64, BK=32, 4x4.
// BOTH K-tiles' GMEM loads are issued upfront (MLP=12, one latency
// wave) before the compute loop. MODE 0: qkv; 1: scores; 2: ff1.
// ============================================================
template <int MODE>
__global__ void __launch_bounds__(256, 2) gemmA_kernel(
    const float* __restrict__ W0, const float* __restrict__ W1,
    const float* __restrict__ W2, const float* __restrict__ tau) {
    __shared__ __align__(16) float As[2][32][36];
    __shared__ __align__(16) float Ws[2][32][68];
    __shared__ __align__(16) float red[32][68];
    const int tid = threadIdx.x;
    const int wg = tid >> 7;
    const int wtid = tid & 127;
    const int m0 = blockIdx.x * 32;
    const int n0 = blockIdx.y * 64;

    const float* Ap;
    const float* Wp;
    if (MODE == 0) {
        Ap = g_xn;
        int sec = n0 >> 7;
        Wp = (sec == 0 ? W0 : (sec == 1 ? W1 : W2)) + (n0 & 127) * 128;
    } else if (MODE == 1) {
        int b = blockIdx.z;
        Ap = g_q + b * N_ * D_;
        Wp = g_k + b * N_ * D_;
    } else {
        Ap = g_xn;
        Wp = W0 + n0 * 128;
    }

    const int kq = wtid & 7, l = wtid >> 3;
    float acc[4][4];
#pragma unroll
    for (int r = 0; r < 4; r++)
#pragma unroll
        for (int c = 0; c < 4; c++) acc[r][c] = NEG;
    const int r0 = (wtid >> 4) * 4, c0 = (wtid & 15) * 4;

    // ---- front-load BOTH K-tiles into registers ----
    float4 pa[2][2], pw[2][4];
#pragma unroll
    for (int t = 0; t < 2; t++) {
        int k0 = wg * 64 + t * 32;
#pragma unroll
        for (int p = 0; p < 2; p++) {
            int row = l + p * 16;
            if (MODE == 1 && (m0 + row) >= N_) pa[t][p] = make_float4(NEG, NEG, NEG, NEG);
            else pa[t][p] = *(const float4*)(Ap + (m0 + row) * 128 + k0 + kq * 4);
        }
#pragma unroll
        for (int p = 0; p < 4; p++) {
            int nl = l + p * 16;
            if (MODE == 1 && (n0 + nl) >= N_) pw[t][p] = make_float4(NEG, NEG, NEG, NEG);
            else {
                int wrow = (MODE == 1) ? (n0 + nl) : nl;
                pw[t][p] = *(const float4*)(Wp + wrow * 128 + k0 + kq * 4);
            }
        }
    }

#pragma unroll
    for (int t = 0; t < 2; t++) {
#pragma unroll
        for (int p = 0; p < 2; p++) {
            int row = l + p * 16;
            As[wg][kq * 4 + 0][row] = pa[t][p].x; As[wg][kq * 4 + 1][row] = pa[t][p].y;
            As[wg][kq * 4 + 2][row] = pa[t][p].z; As[wg][kq * 4 + 3][row] = pa[t][p].w;
        }
#pragma unroll
        for (int p = 0; p < 4; p++) {
            int nl = l + p * 16;
            Ws[wg][kq * 4 + 0][nl] = pw[t][p].x; Ws[wg][kq * 4 + 1][nl] = pw[t][p].y;
            Ws[wg][kq * 4 + 2][nl] = pw[t][p].z; Ws[wg][kq * 4 + 3][nl] = pw[t][p].w;
        }
        __syncthreads();
#pragma unroll
        for (int kk = 0; kk < 32; kk++) {
            float4 a = *(const float4*)&As[wg][kk][r0];
            float4 w = *(const float4*)&Ws[wg][kk][c0];
            float ar[4] = {a.x, a.y, a.z, a.w};
            float wr[4] = {w.x, w.y, w.z, w.w};
#pragma unroll
            for (int r = 0; r < 4; r++)
#pragma unroll
                for (int c = 0; c < 4; c++)
                    acc[r][c] = fmaxf(acc[r][c], ar[r] + wr[c]);
        }
        __syncthreads();
    }

    if (wg == 1) {
#pragma unroll
        for (int r = 0; r < 4; r++)
            *(float4*)&red[r0 + r][c0] =
                make_float4(acc[r][0], acc[r][1], acc[r][2], acc[r][3]);
    }
    __syncthreads();
    if (wg == 1) return;

#pragma unroll
    for (int r = 0; r < 4; r++) {
        float4 rv = *(const float4*)&red[r0 + r][c0];
        acc[r][0] = fmaxf(acc[r][0], rv.x);
        acc[r][1] = fmaxf(acc[r][1], rv.y);
        acc[r][2] = fmaxf(acc[r][2], rv.z);
        acc[r][3] = fmaxf(acc[r][3], rv.w);
    }

    if (MODE == 0) {
#pragma unroll
        for (int r = 0; r < 4; r++) {
            int gm = m0 + r0 + r;
#pragma unroll
            for (int c = 0; c < 4; c++) {
                int gn = n0 + c0 + c;
                float v = acc[r][c];
                if (gn < 128)       g_q[gm * 128 + gn] = v;
                else if (gn < 256)  g_k[gm * 128 + (gn - 128)] = v;
                else                g_v[gm * 128 + (gn - 256)] = v;
            }
        }
    } else if (MODE == 1) {
        int b = blockIdx.z;
        float* out = g_sc + b * N_ * N_;
#pragma unroll
        for (int r = 0; r < 4; r++) {
            int i = m0 + r0 + r;
            if (i < N_) {
#pragma unroll
                for (int c = 0; c < 4; c++) {
                    int j = n0 + c0 + c;
                    if (j < N_) out[i * N_ + j] = acc[r][c];
                }
            }
        }
    } else {
        float tv = tau[0];
#pragma unroll
        for (int r = 0; r < 4; r++) {
            int gm = m0 + r0 + r;
#pragma unroll
            for (int c = 0; c < 4; c++)
                g_ff[gm * 256 + n0 + c0 + c] = fmaxf(acc[r][c], tv);
        }
    }
}

// ============================================================
// Row-fused config (split-K4): 1024 threads = 4 groups of 256.
// BM=16, BN=128, BK=16, software-pipelined GMEM prefetch.
// Reduction buffers alias tile buffers.
// ============================================================
constexpr int AS_BYTES = 4 * 16 * 18 * 4;        // 4608
constexpr int WS_BYTES = 4 * 16 * 132 * 4;       // 33792
constexpr int SBUF_BYTES = AS_BYTES + WS_BYTES;  // 38400

DEV_INLINE void innerB16(const float (&As)[16][18], const float (&Ws)[16][132],
                         float (&acc)[2][4], int r0, int c0) {
#pragma unroll
    for (int kk = 0; kk < 16; kk++) {
        float a0 = As[kk][r0], a1 = As[kk][r0 + 1];
        float4 w = *(const float4*)&Ws[kk][c0];
        acc[0][0] = fmaxf(acc[0][0], a0 + w.x);
        acc[0][1] = fmaxf(acc[0][1], a0 + w.y);
        acc[0][2] = fmaxf(acc[0][2], a0 + w.z);
        acc[0][3] = fmaxf(acc[0][3], a0 + w.w);
        acc[1][0] = fmaxf(acc[1][0], a1 + w.x);
        acc[1][1] = fmaxf(acc[1][1], a1 + w.y);
        acc[1][2] = fmaxf(acc[1][2], a1 + w.z);
        acc[1][3] = fmaxf(acc[1][3], a1 + w.w);
    }
}

// embed: patchify + trop_mm(embed_W) + pos + pnorm. K=256, pipelined.
__global__ void __launch_bounds__(1024) embed_kernel(
    const float* __restrict__ x, const float* __restrict__ eW,
    const float* __restrict__ pos) {
    __shared__ __align__(16) char sbuf[SBUF_BYTES];
    float (*As)[16][18]  = reinterpret_cast<float(*)[16][18]>(sbuf);
    float (*Ws)[16][132] = reinterpret_cast<float(*)[16][132]>(sbuf + AS_BYTES);
    float (*red)[16][132] = reinterpret_cast<float(*)[16][132]>(sbuf);  // alias (post-loop)
    const int tid = threadIdx.x;
    const int wg = tid >> 8;
    const int wtid = tid & 255;
    const int m0 = blockIdx.x * 16;
    const int r0 = (wtid >> 5) * 2, c0 = (wtid & 31) * 4;
    float acc[2][4];
#pragma unroll
    for (int r = 0; r < 2; r++)
#pragma unroll
        for (int c = 0; c < 4; c++) acc[r][c] = NEG;

    // loader coords
    const int al = wtid >> 2, akq = wtid & 3;       // A: rows 0..15 (wtid<64)
    const int wbase = wtid >> 2, wkq = wtid & 3;    // W: 64 row-slots

    // patch base address (valid deref only when wtid<64)
    int gm = m0 + (al & 15);
    int bb = gm / 196, n = gm - bb * 196;
    int gy = n / 14, gx = n - gy * 14;
    const float* abase = x + bb * 50176 + (gy * 16) * 224 + gx * 16;

    float4 pa = make_float4(0, 0, 0, 0);
    float4 pw[2];
    {
        int k0 = wg * 16;
        int k = k0 + akq * 4, py = k >> 4, px = k & 15;
        if (wtid < 64) pa = *(const float4*)(abase + py * 224 + px);
#pragma unroll
        for (int p = 0; p < 2; p++) {
            int nl = wbase + p * 64;
            pw[p] = *(const float4*)(eW + nl * 256 + k0 + wkq * 4);
        }
    }

#pragma unroll
    for (int t = 0; t < 4; t++) {
        if (wtid < 64) {
            As[wg][akq * 4 + 0][al] = pa.x; As[wg][akq * 4 + 1][al] = pa.y;
            As[wg][akq * 4 + 2][al] = pa.z; As[wg][akq * 4 + 3][al] = pa.w;
        }
#pragma unroll
        for (int p = 0; p < 2; p++) {
            int nl = wbase + p * 64;
            Ws[wg][wkq * 4 + 0][nl] = pw[p].x; Ws[wg][wkq * 4 + 1][nl] = pw[p].y;
            Ws[wg][wkq * 4 + 2][nl] = pw[p].z; Ws[wg][wkq * 4 + 3][nl] = pw[p].w;
        }
        __syncthreads();
        if (t < 3) {                       // prefetch next tile (overlaps compute)
            int k0 = ((t + 1) * 4 + wg) * 16;
            int k = k0 + akq * 4, py = k >> 4, px = k & 15;
            if (wtid < 64) pa = *(const float4*)(abase + py * 224 + px);
#pragma unroll
            for (int p = 0; p < 2; p++) {
                int nl = wbase + p * 64;
                pw[p] = *(const float4*)(eW + nl * 256 + k0 + wkq * 4);
            }
        }
        innerB16(As[wg], Ws[wg], acc, r0, c0);
        __syncthreads();
    }

    if (wg > 0) {
#pragma unroll
        for (int r = 0; r < 2; r++)
            *(float4*)&red[wg - 1][r0 + r][c0] =
                make_float4(acc[r][0], acc[r][1], acc[r][2], acc[r][3]);
    }
    __syncthreads();
    if (wg > 0) return;

#pragma unroll
    for (int r = 0; r < 2; r++) {
#pragma unroll
        for (int g = 0; g < 3; g++) {
            float4 rv = *(const float4*)&red[g][r0 + r][c0];
            acc[r][0] = fmaxf(acc[r][0], rv.x);
            acc[r][1] = fmaxf(acc[r][1], rv.y);
            acc[r][2] = fmaxf(acc[r][2], rv.z);
            acc[r][3] = fmaxf(acc[r][3], rv.w);
        }
        int gmo = m0 + r0 + r;
        int nn = gmo % 196;
        float h[4];
#pragma unroll
        for (int c = 0; c < 4; c++) h[c] = acc[r][c] + pos[nn * 128 + c0 + c];
        float dm = warpMax(fmaxf(fmaxf(h[0], h[1]), fmaxf(h[2], h[3])));
        int base = gmo * 128 + c0;
#pragma unroll
        for (int c = 0; c < 4; c++) {
            g_h[base + c] = h[c];
            g_xn[base + c] = h[c] - dm;
        }
    }
}

// ============================================================
// attnout: FULL-K-RESIDENT (R9 structure, unchanged).
// ============================================================
constexpr int VS_F = 132;
constexpr int SS_F = 20;
constexpr int ATT_DYN = (N_ * VS_F + N_ * SS_F) * 4;   // 119,168 B

__global__ void __launch_bounds__(1024) attnout_kernel() {
    extern __shared__ __align__(16) float smem[];
    float* Vs = smem;                 // [196][VS_F]
    float* Ss = smem + N_ * VS_F;     // [196][SS_F]
    float* red = smem;                // alias over Vs post-mainloop

    const int tid = threadIdx.x;
    const int b = blockIdx.y;
    const int m0 = blockIdx.x * 16;
    const float* Ap = g_sc + b * N_ * N_;
    const float* Vp = g_v + b * N_ * D_;

    for (int idx = tid; idx < N_ * 32; idx += 1024) {
        int j = idx >> 5, q = idx & 31;
        *(float4*)(Vs + j * VS_F + q * 4) = *(const float4*)(Vp + j * 128 + q * 4);
    }
    if (tid < 16 * 49) {
        int i = tid / 49, jq = tid - i * 49;
        int gi = m0 + i;
        float4 s = (gi < N_) ? *(const float4*)(Ap + gi * N_ + jq * 4)
                             : make_float4(NEG, NEG, NEG, NEG);
        Ss[(jq * 4 + 0) * SS_F + i] = s.x;
        Ss[(jq * 4 + 1) * SS_F + i] = s.y;
        Ss[(jq * 4 + 2) * SS_F + i] = s.z;
        Ss[(jq * 4 + 3) * SS_F + i] = s.w;
    }
    __syncthreads();

    const int wg = tid >> 7;
    const int wt = tid & 127;
    const int r0 = (wt >> 5) * 4;
    const int c0 = (wt & 31) * 4;
    const int jlo = wg * 24 + (wg < 4 ? wg : 4);
    const int jcnt = 24 + (wg < 4 ? 1 : 0);

    float acc[4][4];
#pragma unroll
    for (int r = 0; r < 4; r++)
#pragma unroll
        for (int c = 0; c < 4; c++) acc[r][c] = NEG;

    const float* ssp = Ss + jlo * SS_F + r0;
    const float* vsp = Vs + jlo * VS_F + c0;
#pragma unroll 5
    for (int t = 0; t < jcnt; t++) {
        float4 a = *(const float4*)ssp;  ssp += SS_F;
        float4 w = *(const float4*)vsp;  vsp += VS_F;
        float ar[4] = {a.x, a.y, a.z, a.w};
        float wr[4] = {w.x, w.y, w.z, w.w};
#pragma unroll
        for (int r = 0; r < 4; r++)
#pragma unroll
            for (int c = 0; c < 4; c++)
                acc[r][c] = fmaxf(acc[r][c], ar[r] + wr[c]);
    }
    __syncthreads();

    if (wg > 0) {
#pragma unroll
        for (int r = 0; r < 4; r++)
            *(float4*)(red + ((wg - 1) * 16 + r0 + r) * VS_F + c0) =
                make_float4(acc[r][0], acc[r][1], acc[r][2], acc[r][3]);
    }
    __syncthreads();
    if (wg > 0) return;

    const int lane = wt & 31;
#pragma unroll
    for (int r = 0; r < 4; r++) {
        int i = m0 + r0 + r;
        if (i < N_) {
#pragma unroll
            for (int g = 0; g < 7; g++) {
                float4 rv = *(const float4*)(red + (g * 16 + r0 + r) * VS_F + c0);
                acc[r][0] = fmaxf(acc[r][0], rv.x);
                acc[r][1] = fmaxf(acc[r][1], rv.y);
                acc[r][2] = fmaxf(acc[r][2], rv.z);
                acc[r][3] = fmaxf(acc[r][3], rv.w);
            }
            float rm = NEG;
            for (int j = lane; j < N_; j += 32)
                rm = fmaxf(rm, Ss[j * SS_F + r0 + r]);
            rm = warpMax(rm);
            float o[4];
#pragma unroll
            for (int c = 0; c < 4; c++) o[c] = acc[r][c] - rm;
            float dm = warpMax(fmaxf(fmaxf(o[0], o[1]), fmaxf(o[2], o[3])));
            int base = (b * 196 + i) * 128 + c0;
            float nx[4];
#pragma unroll
            for (int c = 0; c < 4; c++)
                nx[c] = fmaxf(g_h[base + c], o[c] - dm);
            float dm2 = warpMax(fmaxf(fmaxf(nx[0], nx[1]), fmaxf(nx[2], nx[3])));
#pragma unroll
            for (int c = 0; c < 4; c++) {
                g_h[base + c] = nx[c];
                g_xn[base + c] = nx[c] - dm2;
            }
        }
    }
}

// ff2: trop_mm(g_ff, f2W), K=256, pipelined; pnorm; residual; pnorm.
__global__ void __launch_bounds__(1024) ff2_kernel(const float* __restrict__ W) {
    __shared__ __align__(16) char sbuf[SBUF_BYTES];
    float (*As)[16][18]  = reinterpret_cast<float(*)[16][18]>(sbuf);
    float (*Ws)[16][132] = reinterpret_cast<float(*)[16][132]>(sbuf + AS_BYTES);
    float (*red)[16][132] = reinterpret_cast<float(*)[16][132]>(sbuf);
    const int tid = threadIdx.x;
    const int wg = tid >> 8;
    const int wtid = tid & 255;
    const int m0 = blockIdx.x * 16;
    const int r0 = (wtid >> 5) * 2, c0 = (wtid & 31) * 4;
    float acc[2][4];
#pragma unroll
    for (int r = 0; r < 2; r++)
#pragma unroll
        for (int c = 0; c < 4; c++) acc[r][c] = NEG;

    const int al = wtid >> 2, akq = wtid & 3;
    const int wbase = wtid >> 2, wkq = wtid & 3;

    float4 pa = make_float4(0, 0, 0, 0);
    float4 pw[2];
    {
        int k0 = wg * 16;
        if (wtid < 64)
            pa = *(const float4*)(g_ff + (m0 + al) * 256 + k0 + akq * 4);
#pragma unroll
        for (int p = 0; p < 2; p++) {
            int nl = wbase + p * 64;
            pw[p] = *(const float4*)(W + nl * 256 + k0 + wkq * 4);
        }
    }

#pragma unroll
    for (int t = 0; t < 4; t++) {
        if (wtid < 64) {
            As[wg][akq * 4 + 0][al] = pa.x; As[wg][akq * 4 + 1][al] = pa.y;
            As[wg][akq * 4 + 2][al] = pa.z; As[wg][akq * 4 + 3][al] = pa.w;
        }
#pragma unroll
        for (int p = 0; p < 2; p++) {
            int nl = wbase + p * 64;
            Ws[wg][wkq * 4 + 0][nl] = pw[p].x; Ws[wg][wkq * 4 + 1][nl] = pw[p].y;
            Ws[wg][wkq * 4 + 2][nl] = pw[p].z; Ws[wg][wkq * 4 + 3][nl] = pw[p].w;
        }
        __syncthreads();
        if (t < 3) {
            int k0 = ((t + 1) * 4 + wg) * 16;
            if (wtid < 64)
                pa = *(const float4*)(g_ff + (m0 + al) * 256 + k0 + akq * 4);
#pragma unroll
            for (int p = 0; p < 2; p++) {
                int nl = wbase + p * 64;
                pw[p] = *(const float4*)(W + nl * 256 + k0 + wkq * 4);
            }
        }
        innerB16(As[wg], Ws[wg], acc, r0, c0);
        __syncthreads();
    }

    if (wg > 0) {
#pragma unroll
        for (int r = 0; r < 2; r++)
            *(float4*)&red[wg - 1][r0 + r][c0] =
                make_float4(acc[r][0], acc[r][1], acc[r][2], acc[r][3]);
    }
    __syncthreads();
    if (wg > 0) return;

#pragma unroll
    for (int r = 0; r < 2; r++) {
#pragma unroll
        for (int g = 0; g < 3; g++) {
            float4 rv = *(const float4*)&red[g][r0 + r][c0];
            acc[r][0] = fmaxf(acc[r][0], rv.x);
            acc[r][1] = fmaxf(acc[r][1], rv.y);
            acc[r][2] = fmaxf(acc[r][2], rv.z);
            acc[r][3] = fmaxf(acc[r][3], rv.w);
        }
        int gm = m0 + r0 + r;
        float dm = warpMax(fmaxf(fmaxf(acc[r][0], acc[r][1]), fmaxf(acc[r][2], acc[r][3])));
        int base = gm * 128 + c0;
        float nx[4];
#pragma unroll
        for (int c = 0; c < 4; c++)
            nx[c] = fmaxf(g_h[base + c], acc[r][c] - dm);
        float dm2 = warpMax(fmaxf(fmaxf(nx[0], nx[1]), fmaxf(nx[2], nx[3])));
#pragma unroll
        for (int c = 0; c < 4; c++) {
            g_h[base + c] = nx[c];
            g_xn[base + c] = nx[c] - dm2;
        }
    }
}

__global__ void __launch_bounds__(512) pool_kernel() {
    __shared__ float sm[4][128];
    int b = blockIdx.x;
    int d = threadIdx.x & 127;
    int q = threadIdx.x >> 7;
    float m = NEG;
    for (int n = q; n < N_; n += 4)
        m = fmaxf(m, g_h[(b * N_ + n) * D_ + d]);
    sm[q][d] = m;
    __syncthreads();
    if (q == 0) {
        m = fmaxf(fmaxf(sm[0][d], sm[1][d]), fmaxf(sm[2][d], sm[3][d]));
        g_pool[b * D_ + d] = m;
    }
}

__global__ void __launch_bounds__(256) head_kernel(
    const float* __restrict__ hW, const float* __restrict__ ls,
    float* __restrict__ out) {
    __shared__ float sp[128];
    const int b = blockIdx.y;
    const int tid = threadIdx.x;
    if (tid < 128) sp[tid] = g_pool[b * 128 + tid];
    __syncthreads();
    int c = blockIdx.x * 256 + tid;
    if (c < C_) {
        float acc = NEG;
#pragma unroll 8
        for (int d = 0; d < 128; d += 4) {
            float4 w = *(const float4*)(hW + c * 128 + d);
            acc = fmaxf(acc, sp[d + 0] + w.x);
            acc = fmaxf(acc, sp[d + 1] + w.y);
            acc = fmaxf(acc, sp[d + 2] + w.z);
            acc = fmaxf(acc, sp[d + 3] + w.w);
        }
        out[b * C_ + c] = acc * ls[0];
    }
}

extern "C" void kernel_launch(void* const* d_in, const int* in_sizes, int n_in,
                              void* d_out, int out_size) {
    const float* x   = (const float*)d_in[0];
    const float* eW  = (const float*)d_in[1];
    const float* pos = (const float*)d_in[2];
    const float* qW[2]  = {(const float*)d_in[3],  (const float*)d_in[9]};
    const float* kW[2]  = {(const float*)d_in[4],  (const float*)d_in[10]};
    const float* vW[2]  = {(const float*)d_in[5],  (const float*)d_in[11]};
    const float* f1[2]  = {(const float*)d_in[6],  (const float*)d_in[12]};
    const float* f2[2]  = {(const float*)d_in[7],  (const float*)d_in[13]};
    const float* tau[2] = {(const float*)d_in[8],  (const float*)d_in[14]};
    const float* hW = (const float*)d_in[15];
    const float* ls = (const float*)d_in[16];
    float* out = (float*)d_out;

    cudaFuncSetAttribute(attnout_kernel,
                         cudaFuncAttributeMaxDynamicSharedMemorySize, ATT_DYN);

    embed_kernel<<<98, 1024>>>(x, eW, pos);
    for (int l = 0; l < 2; l++) {
        gemmA_kernel<0><<<dim3(49, 6), 256>>>(qW[l], kW[l], vW[l], nullptr);
        gemmA_kernel<1><<<dim3(7, 4, 8), 256>>>(nullptr, nullptr, nullptr, nullptr);
        attnout_kernel<<<dim3(13, 8), 1024, ATT_DYN>>>();
        gemmA_kernel<2><<<dim3(49, 4), 256>>>(f1[l], nullptr, nullptr, tau[l]);
        ff2_kernel<<<98, 1024>>>(f2[l]);
    }
    pool_kernel<<<8, 512>>>();
    head_kernel<<<dim3(4, 8), 256>>>(hW, ls, out);
}